// round 11
// baseline (speedup 1.0000x reference)
#include <cuda_runtime.h>
#include <cuda_bf16.h>
#include <cstddef>
#include <cstdint>

// SparseConv: out[out_map[k,m]] += x[in_map[k,m]] @ W[k]   (K=27, M=65536, Cin=Cout=64)
//
// Round 11: R10 + double-buffered cp.async pipeline at constant smem/occupancy.
//   - tiles shrink to 64 edges; two A buffers (hi/lo) fit in the same 55.3KB -> occ 3
//   - gather(t+1) committed before wait_group on gather(t): async copies overlap MMA
//   - pre-pass kernel folds out-zeroing + x fp32->bf16 hi/lo split into one launch

#define CIN     64
#define COUT    64
#define THREADS 256
#define CTAS_X  16

#define STRIDE_A 144
#define STRIDE_B 144

#define HBUF     (64 * STRIDE_A)             // 9216 B per (buf, plane)
// A: buf0 hi | buf0 lo | buf1 hi | buf1 lo
#define SM_B_HI  (4 * HBUF)                  // 36864
#define SM_B_LO  (SM_B_HI + CIN * STRIDE_B)  // 46080
#define SM_TOTAL (SM_B_LO + CIN * STRIDE_B)  // 55296 B -> 3 CTAs/SM

// global scratch: bf16 hi/lo planes of x (128 B per row), uint2-chunked
#define NMAX_CHUNK (262144 * 16)
__device__ __align__(16) uint2 g_xhi[NMAX_CHUNK];
__device__ __align__(16) uint2 g_xlo[NMAX_CHUNK];

__device__ __forceinline__ uint32_t smem_u32(const void* p) {
    uint32_t a;
    asm("{ .reg .u64 t; cvta.to.shared.u64 t, %1; cvt.u32.u64 %0, t; }" : "=r"(a) : "l"(p));
    return a;
}
__device__ __forceinline__ uint32_t pack_bf16x2(float hi_elem, float lo_elem) {
    uint32_t r;
    asm("cvt.rn.bf16x2.f32 %0, %1, %2;" : "=r"(r) : "f"(hi_elem), "f"(lo_elem));
    return r;  // [15:0]=bf16(lo_elem), [31:16]=bf16(hi_elem)
}

#define CP_ASYNC16(dst, src) \
    asm volatile("cp.async.cg.shared.global [%0], [%1], 16;" :: "r"(dst), "l"(src) : "memory")
#define CP_COMMIT()  asm volatile("cp.async.commit_group;" ::: "memory")
#define CP_WAIT0()   asm volatile("cp.async.wait_group 0;" ::: "memory")
#define CP_WAIT1()   asm volatile("cp.async.wait_group 1;" ::: "memory")

#define LDSM_X4(r, addr) \
    asm volatile("ldmatrix.sync.aligned.m8n8.x4.shared.b16 {%0,%1,%2,%3}, [%4];" \
        : "=r"((r)[0]), "=r"((r)[1]), "=r"((r)[2]), "=r"((r)[3]) : "r"(addr))

#define LDSM_X4_T(r, addr) \
    asm volatile("ldmatrix.sync.aligned.m8n8.x4.trans.shared.b16 {%0,%1,%2,%3}, [%4];" \
        : "=r"((r)[0]), "=r"((r)[1]), "=r"((r)[2]), "=r"((r)[3]) : "r"(addr))

#define MMA_BF16(c, a, b0, b1) \
    asm volatile("mma.sync.aligned.m16n8k16.row.col.f32.bf16.bf16.f32 " \
        "{%0,%1,%2,%3}, {%4,%5,%6,%7}, {%8,%9}, {%0,%1,%2,%3};" \
        : "+f"((c)[0]), "+f"((c)[1]), "+f"((c)[2]), "+f"((c)[3]) \
        : "r"((a)[0]), "r"((a)[1]), "r"((a)[2]), "r"((a)[3]), "r"(b0), "r"(b1))

__device__ __forceinline__ void red_add_v4(float* dst, float a, float b, float c, float d) {
    asm volatile("red.global.add.v4.f32 [%0], {%1, %2, %3, %4};"
                 :: "l"(dst), "f"(a), "f"(b), "f"(c), "f"(d) : "memory");
}

// ---------- pre-pass: zero out + split x fp32 -> bf16 hi/lo planes ----------
__global__ void __launch_bounds__(256) prep_kernel(
    const float* __restrict__ x, float* __restrict__ out, int total4, int out4)
{
    const int i = blockIdx.x * 256 + threadIdx.x;
    if (i < out4) ((float4*)out)[i] = make_float4(0.f, 0.f, 0.f, 0.f);
    if (i < total4) {
        const float4 v = ((const float4*)x)[i];
        const uint32_t h0 = pack_bf16x2(v.y, v.x);
        const uint32_t h1 = pack_bf16x2(v.w, v.z);
        const float r0 = v.x - __uint_as_float(h0 << 16);
        const float r1 = v.y - __uint_as_float(h0 & 0xFFFF0000u);
        const float r2 = v.z - __uint_as_float(h1 << 16);
        const float r3 = v.w - __uint_as_float(h1 & 0xFFFF0000u);
        g_xhi[i] = make_uint2(h0, h1);
        g_xlo[i] = make_uint2(pack_bf16x2(r1, r0), pack_bf16x2(r3, r2));
    }
}

// gather one 64-edge tile into buffer b (cp.async, both planes)
__device__ __forceinline__ void gather64(
    uint32_t sb, int b, const int* __restrict__ in_map, int base, int tid)
{
    const char* xhiB = (const char*)g_xhi;
    const char* xloB = (const char*)g_xlo;
    const uint32_t dhi = sb + (uint32_t)(b * 2 * HBUF);
    const uint32_t dlo = dhi + HBUF;
    #pragma unroll
    for (int j = 0; j < 2; j++) {
        const int f = tid + j * THREADS;
        const int e = f >> 3, c = f & 7;
        const int row = in_map[base + e];
        const size_t sboff = (size_t)row * 128 + c * 16;
        const uint32_t doff = (uint32_t)(e * STRIDE_A + c * 16);
        CP_ASYNC16(dhi + doff, xhiB + sboff);
        CP_ASYNC16(dlo + doff, xloB + sboff);
    }
    CP_COMMIT();
}

// ---------- main kernel ----------
__global__ void __launch_bounds__(THREADS, 3) sparse_conv_mma8(
    const float* __restrict__ W,
    const int*   __restrict__ in_map,
    const int*   __restrict__ out_map,
    float*       __restrict__ out,
    int M)
{
    extern __shared__ char smem[];
    const uint32_t sb = smem_u32(smem);
    const int tid  = threadIdx.x;
    const int w    = tid >> 5;
    const int lane = tid & 31;
    const int mg   = w >> 1;        // rows 16*mg .. 16*mg+15 (of 64)
    const int nh   = w & 1;         // cols 32*nh .. 32*nh+31
    const int k    = blockIdx.y;
    const int kM   = k * M;
    const int ntiles = M >> 6;      // 64-edge tiles per k

    // --- stage W[k] -> bf16 hi/lo in smem (once per CTA) ---
    {
        const float* Wk = W + (size_t)k * (CIN * COUT);
        #pragma unroll
        for (int i = 0; i < (CIN * COUT) / THREADS; i++) {
            const int lin = tid + i * THREADS;
            const int c = lin >> 6, n = lin & 63;
            const float wv = Wk[lin];
            const __nv_bfloat16 hv = __float2bfloat16(wv);
            const __nv_bfloat16 lv = __float2bfloat16(wv - __bfloat162float(hv));
            const uint32_t off = (uint32_t)(c * STRIDE_B + n * 2);
            *(__nv_bfloat16*)(smem + SM_B_HI + off) = hv;
            *(__nv_bfloat16*)(smem + SM_B_LO + off) = lv;
        }
    }

    // fragment addressing
    const uint32_t b_off = (uint32_t)((lane & 15) * STRIDE_B + (lane >> 4) * 16 + nh * 64);
    const uint32_t bHi = sb + SM_B_HI + b_off;
    const uint32_t bLo = sb + SM_B_LO + b_off;
    const uint32_t a_off = (uint32_t)((16 * mg + (lane & 15)) * STRIDE_A + (lane >> 4) * 16);

    // epilogue lane mapping
    const bool odd = (lane & 1);
    const int  er0 = 16 * mg + (lane >> 2) + (odd ? 8 : 0);
    const int  q0  = (lane & 2) * 2;

    // --- prologue: gather first tile into buf 0 ---
    int mt = blockIdx.x;
    gather64(sb, 0, in_map, kM + (mt << 6), tid);
    int buf = 0;

    while (mt < ntiles) {
        const int nxt = mt + CTAS_X;

        // commit next tile's gather into the other buffer (overlaps this tile's MMA)
        if (nxt < ntiles) {
            gather64(sb, buf ^ 1, in_map, kM + (nxt << 6), tid);
            CP_WAIT1();      // wait only for THIS tile's group (landed during prev MMA)
        } else {
            CP_WAIT0();
        }
        __syncthreads();     // all threads' copies of buf visible

        // epilogue row prefetch (L2 LDG overlaps MMA)
        const int orow = out_map[kM + (mt << 6) + er0];

        // --- MMA: 4 k-steps x (2x2 halves) x 3 terms = 48 mma/warp ---
        float acc[4][4];
        #pragma unroll
        for (int j = 0; j < 4; j++)
            #pragma unroll
            for (int i = 0; i < 4; i++) acc[j][i] = 0.0f;

        const uint32_t aHi = sb + (uint32_t)(buf * 2 * HBUF) + a_off;
        const uint32_t aLo = aHi + HBUF;
        #pragma unroll
        for (int s = 0; s < 4; s++) {
            uint32_t bh[2][4], bl[2][4];
            const uint32_t so = (uint32_t)(s * 16 * STRIDE_B);
            LDSM_X4_T(bh[0], bHi + so);
            LDSM_X4_T(bh[1], bHi + so + 32);
            LDSM_X4_T(bl[0], bLo + so);
            LDSM_X4_T(bl[1], bLo + so + 32);
            uint32_t ah[4], al[4];
            LDSM_X4(ah, aHi + (uint32_t)(s * 32));
            LDSM_X4(al, aLo + (uint32_t)(s * 32));
            #pragma unroll
            for (int p = 0; p < 2; p++) {
                MMA_BF16(acc[2 * p],     ah, bh[p][0], bh[p][1]);
                MMA_BF16(acc[2 * p + 1], ah, bh[p][2], bh[p][3]);
                MMA_BF16(acc[2 * p],     ah, bl[p][0], bl[p][1]);
                MMA_BF16(acc[2 * p + 1], ah, bl[p][2], bl[p][3]);
                MMA_BF16(acc[2 * p],     al, bh[p][0], bh[p][1]);
                MMA_BF16(acc[2 * p + 1], al, bh[p][2], bh[p][3]);
            }
        }

        // --- epilogue: shfl pair-swap -> red.global.add.v4 ---
        {
            float* obase = out + (size_t)orow * COUT + nh * 32 + q0;
            #pragma unroll
            for (int j = 0; j < 4; j++) {
                float* c = acc[j];
                const float s0 = __shfl_xor_sync(0xFFFFFFFFu, c[0], 1);
                const float s1 = __shfl_xor_sync(0xFFFFFFFFu, c[1], 1);
                const float s2 = __shfl_xor_sync(0xFFFFFFFFu, c[2], 1);
                const float s3 = __shfl_xor_sync(0xFFFFFFFFu, c[3], 1);
                const float v0 = odd ? s2 : c[0];
                const float v1 = odd ? s3 : c[1];
                const float v2 = odd ? c[2] : s0;
                const float v3 = odd ? c[3] : s1;
                red_add_v4(obase + 8 * j, v0, v1, v2, v3);
            }
        }
        __syncthreads();   // buf's LDSM done before next iteration's gather overwrites buf
        mt = nxt;
        buf ^= 1;
    }
}

extern "C" void kernel_launch(void* const* d_in, const int* in_sizes, int n_in,
                              void* d_out, int out_size)
{
    const float* x       = (const float*)d_in[0];
    const float* W       = (const float*)d_in[1];
    const int*   in_map  = (const int*)d_in[2];
    const int*   out_map = (const int*)d_in[3];
    float*       out     = (float*)d_out;

    const int K = in_sizes[1] / (CIN * COUT);   // 27
    const int M = in_sizes[2] / K;              // 65536
    const int total4 = in_sizes[0] / 4;
    const int out4   = out_size / 4;
    const int pmax   = total4 > out4 ? total4 : out4;

    static bool attr_set = false;
    if (!attr_set) {
        cudaFuncSetAttribute(sparse_conv_mma8,
                             cudaFuncAttributeMaxDynamicSharedMemorySize, SM_TOTAL);
        attr_set = true;
    }

    prep_kernel<<<(pmax + 255) / 256, 256>>>(x, out, total4, out4);

    dim3 grid(CTAS_X, K);
    sparse_conv_mma8<<<grid, THREADS, SM_TOTAL>>>(W, in_map, out_map, out, M);
}

// round 12
// speedup vs baseline: 1.0509x; 1.0509x over previous
#include <cuda_runtime.h>
#include <cuda_bf16.h>
#include <cstddef>
#include <cstdint>

// SparseConv: out[out_map[k,m]] += x[in_map[k,m]] @ W[k]   (K=27, M=65536, Cin=Cout=64)
//
// Round 12: R10 main kernel (212.4us measured) + loop reorder so the per-tile
// cp.async wait is covered by the previous tile's epilogue:
//   wait(t) -> MMA(t) -> sync -> issue gather(t+1) -> epilogue(t) -> loop
// plus R11's folded prep kernel (zero out + fp32->bf16 hi/lo split, one launch).
//   128-edge tiles, single A buffer, B staged per CTA, occ 3 (launch_bounds 256,3).

#define CIN     64
#define COUT    64
#define THREADS 256
#define CTAS_X  16

#define STRIDE_A 144
#define STRIDE_B 144

#define ABUF     (128 * STRIDE_A)            // 18432 B per hi/lo plane
#define SM_A_HI  0
#define SM_A_LO  ABUF                        // 18432
#define SM_B_HI  (2 * ABUF)                  // 36864
#define SM_B_LO  (SM_B_HI + CIN * STRIDE_B)  // 46080
#define SM_TOTAL (SM_B_LO + CIN * STRIDE_B)  // 55296 B -> 3 CTAs/SM

// global scratch: bf16 hi/lo planes of x (128 B rows), uint2-chunked
#define NMAX_CHUNK (262144 * 16)
__device__ __align__(16) uint2 g_xhi[NMAX_CHUNK];
__device__ __align__(16) uint2 g_xlo[NMAX_CHUNK];

__device__ __forceinline__ uint32_t smem_u32(const void* p) {
    uint32_t a;
    asm("{ .reg .u64 t; cvta.to.shared.u64 t, %1; cvt.u32.u64 %0, t; }" : "=r"(a) : "l"(p));
    return a;
}
__device__ __forceinline__ uint32_t pack_bf16x2(float hi_elem, float lo_elem) {
    uint32_t r;
    asm("cvt.rn.bf16x2.f32 %0, %1, %2;" : "=r"(r) : "f"(hi_elem), "f"(lo_elem));
    return r;  // [15:0]=bf16(lo_elem), [31:16]=bf16(hi_elem)
}

#define CP_ASYNC16(dst, src) \
    asm volatile("cp.async.cg.shared.global [%0], [%1], 16;" :: "r"(dst), "l"(src) : "memory")
#define CP_COMMIT()  asm volatile("cp.async.commit_group;" ::: "memory")
#define CP_WAIT0()   asm volatile("cp.async.wait_group 0;" ::: "memory")

#define LDSM_X4(r, addr) \
    asm volatile("ldmatrix.sync.aligned.m8n8.x4.shared.b16 {%0,%1,%2,%3}, [%4];" \
        : "=r"((r)[0]), "=r"((r)[1]), "=r"((r)[2]), "=r"((r)[3]) : "r"(addr))

#define LDSM_X4_T(r, addr) \
    asm volatile("ldmatrix.sync.aligned.m8n8.x4.trans.shared.b16 {%0,%1,%2,%3}, [%4];" \
        : "=r"((r)[0]), "=r"((r)[1]), "=r"((r)[2]), "=r"((r)[3]) : "r"(addr))

#define MMA_BF16(c, a, b0, b1) \
    asm volatile("mma.sync.aligned.m16n8k16.row.col.f32.bf16.bf16.f32 " \
        "{%0,%1,%2,%3}, {%4,%5,%6,%7}, {%8,%9}, {%0,%1,%2,%3};" \
        : "+f"((c)[0]), "+f"((c)[1]), "+f"((c)[2]), "+f"((c)[3]) \
        : "r"((a)[0]), "r"((a)[1]), "r"((a)[2]), "r"((a)[3]), "r"(b0), "r"(b1))

__device__ __forceinline__ void red_add_v4(float* dst, float a, float b, float c, float d) {
    asm volatile("red.global.add.v4.f32 [%0], {%1, %2, %3, %4};"
                 :: "l"(dst), "f"(a), "f"(b), "f"(c), "f"(d) : "memory");
}

// ---------- prep: zero out + split x fp32 -> bf16 hi/lo planes (one launch) ----------
__global__ void __launch_bounds__(256) prep_kernel(
    const float* __restrict__ x, float* __restrict__ out, int total4, int out4)
{
    const int i = blockIdx.x * 256 + threadIdx.x;
    if (i < out4) ((float4*)out)[i] = make_float4(0.f, 0.f, 0.f, 0.f);
    if (i < total4) {
        const float4 v = ((const float4*)x)[i];
        const uint32_t h0 = pack_bf16x2(v.y, v.x);
        const uint32_t h1 = pack_bf16x2(v.w, v.z);
        const float r0 = v.x - __uint_as_float(h0 << 16);
        const float r1 = v.y - __uint_as_float(h0 & 0xFFFF0000u);
        const float r2 = v.z - __uint_as_float(h1 << 16);
        const float r3 = v.w - __uint_as_float(h1 & 0xFFFF0000u);
        g_xhi[i] = make_uint2(h0, h1);
        g_xlo[i] = make_uint2(pack_bf16x2(r1, r0), pack_bf16x2(r3, r2));
    }
}

// issue cp.async gather of one 128-edge tile (both planes), commit group
__device__ __forceinline__ void gather128(
    uint32_t sb, const int* __restrict__ in_map, int base, int tid)
{
    const char* xhiB = (const char*)g_xhi;
    const char* xloB = (const char*)g_xlo;
    #pragma unroll
    for (int j = 0; j < 4; j++) {
        const int f = tid + j * THREADS;
        const int e = f >> 3, c = f & 7;
        const int row = in_map[base + e];
        const size_t sboff = (size_t)row * 128 + c * 16;
        const uint32_t doff = (uint32_t)(e * STRIDE_A + c * 16);
        CP_ASYNC16(sb + SM_A_HI + doff, xhiB + sboff);
        CP_ASYNC16(sb + SM_A_LO + doff, xloB + sboff);
    }
    CP_COMMIT();
}

// ---------- main kernel ----------
__global__ void __launch_bounds__(THREADS, 3) sparse_conv_mma9(
    const float* __restrict__ W,
    const int*   __restrict__ in_map,
    const int*   __restrict__ out_map,
    float*       __restrict__ out,
    int M)
{
    extern __shared__ char smem[];
    const uint32_t sb = smem_u32(smem);
    const int tid  = threadIdx.x;
    const int w    = tid >> 5;
    const int lane = tid & 31;
    const int mg   = w >> 1;        // rows 32*mg .. 32*mg+31
    const int nh   = w & 1;         // cols 32*nh .. 32*nh+31
    const int k    = blockIdx.y;
    const int kM   = k * M;
    const int ntiles = M >> 7;

    // --- stage W[k] -> bf16 hi/lo in smem (once per CTA) ---
    {
        const float* Wk = W + (size_t)k * (CIN * COUT);
        #pragma unroll
        for (int i = 0; i < (CIN * COUT) / THREADS; i++) {
            const int lin = tid + i * THREADS;
            const int c = lin >> 6, n = lin & 63;
            const float wv = Wk[lin];
            const __nv_bfloat16 hv = __float2bfloat16(wv);
            const __nv_bfloat16 lv = __float2bfloat16(wv - __bfloat162float(hv));
            const uint32_t off = (uint32_t)(c * STRIDE_B + n * 2);
            *(__nv_bfloat16*)(smem + SM_B_HI + off) = hv;
            *(__nv_bfloat16*)(smem + SM_B_LO + off) = lv;
        }
    }

    // fragment addressing
    const uint32_t b_off = (uint32_t)((lane & 15) * STRIDE_B + (lane >> 4) * 16 + nh * 64);
    const uint32_t bHi = sb + SM_B_HI + b_off;
    const uint32_t bLo = sb + SM_B_LO + b_off;
    const uint32_t a_off = (uint32_t)((32 * mg + (lane & 15)) * STRIDE_A + (lane >> 4) * 16);
    const uint32_t aHi = sb + SM_A_HI + a_off;
    const uint32_t aLo = sb + SM_A_LO + a_off;

    // epilogue lane mapping
    const bool odd = (lane & 1);
    const int  er0 = 32 * mg + (lane >> 2) + (odd ? 8 : 0);
    const int  q0  = (lane & 2) * 2;

    // --- prologue: issue first gather ---
    int mt = blockIdx.x;
    gather128(sb, in_map, kM + (mt << 7), tid);

    while (mt < ntiles) {
        const int nxt = mt + CTAS_X;
        const int m0 = mt << 7;

        // epilogue rows (in flight during wait+MMA)
        const int orow0 = out_map[kM + m0 + er0];
        const int orow1 = out_map[kM + m0 + er0 + 16];

        CP_WAIT0();          // gather(mt) landed (covered by previous tile's epilogue)
        __syncthreads();     // visibility of all threads' copies (and W on first iter)

        // --- MMA: s-outer; B hi+lo from smem once per s; t inner ---
        float acc[2][4][4];
        #pragma unroll
        for (int t = 0; t < 2; t++)
            #pragma unroll
            for (int j = 0; j < 4; j++)
                #pragma unroll
                for (int i = 0; i < 4; i++) acc[t][j][i] = 0.0f;

        #pragma unroll
        for (int s = 0; s < 4; s++) {
            uint32_t bh[2][4], bl[2][4];
            const uint32_t so = (uint32_t)(s * 16 * STRIDE_B);
            LDSM_X4_T(bh[0], bHi + so);
            LDSM_X4_T(bh[1], bHi + so + 32);
            LDSM_X4_T(bl[0], bLo + so);
            LDSM_X4_T(bl[1], bLo + so + 32);
            #pragma unroll
            for (int t = 0; t < 2; t++) {
                uint32_t ah[4], al[4];
                const uint32_t ao = (uint32_t)(t * 16 * STRIDE_A + s * 32);
                LDSM_X4(ah, aHi + ao);
                LDSM_X4(al, aLo + ao);
                #pragma unroll
                for (int p = 0; p < 2; p++) {
                    MMA_BF16(acc[t][2 * p],     ah, bh[p][0], bh[p][1]);
                    MMA_BF16(acc[t][2 * p + 1], ah, bh[p][2], bh[p][3]);
                    MMA_BF16(acc[t][2 * p],     ah, bl[p][0], bl[p][1]);
                    MMA_BF16(acc[t][2 * p + 1], ah, bl[p][2], bl[p][3]);
                    MMA_BF16(acc[t][2 * p],     al, bh[p][0], bh[p][1]);
                    MMA_BF16(acc[t][2 * p + 1], al, bh[p][2], bh[p][3]);
                }
            }
        }

        __syncthreads();     // all warps' LDSM of A done -> buffer free for next gather

        // issue next tile's gather NOW; epilogue below covers the copy latency
        if (nxt < ntiles)
            gather128(sb, in_map, kM + (nxt << 7), tid);

        // --- epilogue: shfl pair-swap -> red.global.add.v4 (covers cp.async) ---
        #pragma unroll
        for (int t = 0; t < 2; t++) {
            const int orow = t ? orow1 : orow0;
            float* obase = out + (size_t)orow * COUT + nh * 32 + q0;
            #pragma unroll
            for (int j = 0; j < 4; j++) {
                float* c = acc[t][j];
                const float s0 = __shfl_xor_sync(0xFFFFFFFFu, c[0], 1);
                const float s1 = __shfl_xor_sync(0xFFFFFFFFu, c[1], 1);
                const float s2 = __shfl_xor_sync(0xFFFFFFFFu, c[2], 1);
                const float s3 = __shfl_xor_sync(0xFFFFFFFFu, c[3], 1);
                const float v0 = odd ? s2 : c[0];
                const float v1 = odd ? s3 : c[1];
                const float v2 = odd ? c[2] : s0;
                const float v3 = odd ? c[3] : s1;
                red_add_v4(obase + 8 * j, v0, v1, v2, v3);
            }
        }

        mt = nxt;
    }
}

extern "C" void kernel_launch(void* const* d_in, const int* in_sizes, int n_in,
                              void* d_out, int out_size)
{
    const float* x       = (const float*)d_in[0];
    const float* W       = (const float*)d_in[1];
    const int*   in_map  = (const int*)d_in[2];
    const int*   out_map = (const int*)d_in[3];
    float*       out     = (float*)d_out;

    const int K = in_sizes[1] / (CIN * COUT);   // 27
    const int M = in_sizes[2] / K;              // 65536
    const int total4 = in_sizes[0] / 4;
    const int out4   = out_size / 4;
    const int pmax   = total4 > out4 ? total4 : out4;

    static bool attr_set = false;
    if (!attr_set) {
        cudaFuncSetAttribute(sparse_conv_mma9,
                             cudaFuncAttributeMaxDynamicSharedMemorySize, SM_TOTAL);
        attr_set = true;
    }

    prep_kernel<<<(pmax + 255) / 256, 256>>>(x, out, total4, out4);

    dim3 grid(CTAS_X, K);
    sparse_conv_mma9<<<grid, THREADS, SM_TOTAL>>>(W, in_map, out_map, out, M);
}

// round 13
// speedup vs baseline: 1.0864x; 1.0337x over previous
#include <cuda_runtime.h>
#include <cstddef>
#include <cstdint>

// SparseConv: out[out_map[k,m]] += x[in_map[k,m]] @ W[k]   (K=27, M=65536, Cin=Cout=64)
//
// Round 13: single-pass TF32 mma.m16n8k8 (drops the 3-term bf16 emulation).
//   - A = raw fp32 x rows, gathered straight into smem via cp.async (no prep kernel,
//     no conversion, no hi/lo planes)
//   - B = W[k] transposed + pre-rounded to tf32 in smem, k-interleaved so each
//     fragment is one LDS.64; stride 272B makes all fragment LDS conflict-free
//   - 64 mma/warp/tile (vs 96), epilogue RED path unchanged (proven)
//   - occ 3 (smem 52.2KB, launch_bounds(256,3)), grid (16,27)

#define CIN     64
#define COUT    64
#define THREADS 256
#define CTAS_X  16

#define STRW     272                 // bytes per row (68 words): conflict-free LDS
#define STRW_W   68                  // words
#define SM_A     0                   // 128 rows * 272 = 34816 B (fp32 x tile)
#define SM_B     34816               // 64 rows * 272  = 17408 B (tf32 W^T)
#define SM_TOTAL (34816 + 17408)     // 52224 B -> 3 CTAs/SM

__device__ __forceinline__ uint32_t smem_u32(const void* p) {
    uint32_t a;
    asm("{ .reg .u64 t; cvta.to.shared.u64 t, %1; cvt.u32.u64 %0, t; }" : "=r"(a) : "l"(p));
    return a;
}
__device__ __forceinline__ uint32_t f2tf32(float f) {
    uint32_t u;
    asm("cvt.rna.tf32.f32 %0, %1;" : "=r"(u) : "f"(f));
    return u;
}

#define CP_ASYNC16(dst, src) \
    asm volatile("cp.async.cg.shared.global [%0], [%1], 16;" :: "r"(dst), "l"(src) : "memory")
#define CP_COMMIT()  asm volatile("cp.async.commit_group;" ::: "memory")
#define CP_WAIT0()   asm volatile("cp.async.wait_group 0;" ::: "memory")

#define MMA_TF32(c, a, b0, b1) \
    asm volatile("mma.sync.aligned.m16n8k8.row.col.f32.tf32.tf32.f32 " \
        "{%0,%1,%2,%3}, {%4,%5,%6,%7}, {%8,%9}, {%0,%1,%2,%3};" \
        : "+f"((c)[0]), "+f"((c)[1]), "+f"((c)[2]), "+f"((c)[3]) \
        : "r"((a)[0]), "r"((a)[1]), "r"((a)[2]), "r"((a)[3]), "r"(b0), "r"(b1))

__device__ __forceinline__ void red_add_v4(float* dst, float a, float b, float c, float d) {
    asm volatile("red.global.add.v4.f32 [%0], {%1, %2, %3, %4};"
                 :: "l"(dst), "f"(a), "f"(b), "f"(c), "f"(d) : "memory");
}

__global__ void __launch_bounds__(THREADS, 3) sparse_conv_tf32(
    const float* __restrict__ x,
    const float* __restrict__ W,
    const int*   __restrict__ in_map,
    const int*   __restrict__ out_map,
    float*       __restrict__ out,
    int M)
{
    extern __shared__ char smem[];
    const uint32_t sb = smem_u32(smem);
    float*    smA = (float*)smem;                 // word-indexed A (fp32)
    uint32_t* smB = (uint32_t*)(smem + SM_B);     // word-indexed B (tf32 bits)
    const int tid  = threadIdx.x;
    const int w    = tid >> 5;
    const int lane = tid & 31;
    const int mg   = w >> 1;        // rows 32*mg .. 32*mg+31
    const int nh   = w & 1;         // cols 32*nh .. 32*nh+31
    const int k    = blockIdx.y;
    const int kM   = k * M;
    const int ntiles = M >> 7;

    // --- stage W[k]^T as tf32, k-interleaved: word[n*68 + s*8 + c],
    //     c = (kk&3)*2 + (kk>>2), kg = s*8+kk  (so each B frag = 1 LDS.64) ---
    {
        const float* Wk = W + (size_t)k * (CIN * COUT);
        #pragma unroll
        for (int i = 0; i < (CIN * COUT) / THREADS; i++) {
            const int lin = tid + i * THREADS;
            const int kg = lin >> 6, n = lin & 63;
            const int s = kg >> 3, kk = kg & 7;
            const int c = ((kk & 3) << 1) | (kk >> 2);
            smB[n * STRW_W + s * 8 + c] = f2tf32(Wk[(size_t)kg * COUT + n]);
        }
    }

    // fragment addressing (word indices)
    // A frag (t,s): lane -> rows r, r+8 at cols s*8+(lane&3), +4
    const int arow = 32 * mg + (lane >> 2);
    const int awrd = arow * STRW_W + (lane & 3);
    // B frag (s,p): lane -> row nh*32 + p*8 + (lane>>2), word pair at s*8 + (lane&3)*2
    const int bwrd = (nh * 32 + (lane >> 2)) * STRW_W + (lane & 3) * 2;

    // epilogue lane mapping (m16n8 C layout, same pair-swap as before)
    const bool odd = (lane & 1);
    const int  er0 = 32 * mg + (lane >> 2) + (odd ? 8 : 0);
    const int  q0  = (lane & 2) * 2;

    for (int mt = blockIdx.x; mt < ntiles; mt += CTAS_X) {
        const int m0 = mt << 7;

        __syncthreads();   // previous tile's LDS readers done before overwrite

        // --- gather: cp.async 128 fp32 x-rows (16B chunks, 8/thread) ---
        #pragma unroll
        for (int j = 0; j < 8; j++) {
            const int f = tid + j * THREADS;
            const int e = f >> 4, q = f & 15;
            const int row = in_map[kM + m0 + e];
            CP_ASYNC16(sb + (uint32_t)(e * STRW + q * 16),
                       x + (size_t)row * CIN + q * 4);
        }
        CP_COMMIT();

        // epilogue rows (LDG in flight during wait)
        const int orow0 = out_map[kM + m0 + er0];
        const int orow1 = out_map[kM + m0 + er0 + 16];

        CP_WAIT0();
        __syncthreads();

        // --- MMA: 8 k-steps x 2 m-tiles x 4 n8-tiles = 64 mma/warp ---
        float acc[2][4][4];
        #pragma unroll
        for (int t = 0; t < 2; t++)
            #pragma unroll
            for (int j = 0; j < 4; j++)
                #pragma unroll
                for (int i = 0; i < 4; i++) acc[t][j][i] = 0.0f;

        #pragma unroll
        for (int s = 0; s < 4; s++) {   // outer over pairs of k-steps to batch B loads
            #pragma unroll
            for (int half = 0; half < 2; half++) {
                const int ks = s * 2 + half;       // k-step 0..7
                // B fragments: 4 n8 tiles, one LDS.64 each
                uint32_t bf[4][2];
                #pragma unroll
                for (int p = 0; p < 4; p++) {
                    const uint2 bv = *(const uint2*)(smB + bwrd + p * 8 * STRW_W + ks * 8);
                    bf[p][0] = bv.x; bf[p][1] = bv.y;
                }
                #pragma unroll
                for (int t = 0; t < 2; t++) {
                    const int aw = awrd + t * 16 * STRW_W + ks * 8;
                    uint32_t af[4];
                    af[0] = f2tf32(smA[aw]);
                    af[1] = f2tf32(smA[aw + 8 * STRW_W]);
                    af[2] = f2tf32(smA[aw + 4]);
                    af[3] = f2tf32(smA[aw + 8 * STRW_W + 4]);
                    #pragma unroll
                    for (int p = 0; p < 4; p++)
                        MMA_TF32(acc[t][p], af, bf[p][0], bf[p][1]);
                }
            }
        }

        // --- epilogue: shfl pair-swap -> red.global.add.v4 ---
        #pragma unroll
        for (int t = 0; t < 2; t++) {
            const int orow = t ? orow1 : orow0;
            float* obase = out + (size_t)orow * COUT + nh * 32 + q0;
            #pragma unroll
            for (int j = 0; j < 4; j++) {
                float* c = acc[t][j];
                const float s0 = __shfl_xor_sync(0xFFFFFFFFu, c[0], 1);
                const float s1 = __shfl_xor_sync(0xFFFFFFFFu, c[1], 1);
                const float s2 = __shfl_xor_sync(0xFFFFFFFFu, c[2], 1);
                const float s3 = __shfl_xor_sync(0xFFFFFFFFu, c[3], 1);
                const float v0 = odd ? s2 : c[0];
                const float v1 = odd ? s3 : c[1];
                const float v2 = odd ? c[2] : s0;
                const float v3 = odd ? c[3] : s1;
                red_add_v4(obase + 8 * j, v0, v1, v2, v3);
            }
        }
    }
}

extern "C" void kernel_launch(void* const* d_in, const int* in_sizes, int n_in,
                              void* d_out, int out_size)
{
    const float* x       = (const float*)d_in[0];
    const float* W       = (const float*)d_in[1];
    const int*   in_map  = (const int*)d_in[2];
    const int*   out_map = (const int*)d_in[3];
    float*       out     = (float*)d_out;

    const int K = in_sizes[1] / (CIN * COUT);   // 27
    const int M = in_sizes[2] / K;              // 65536

    static bool attr_set = false;
    if (!attr_set) {
        cudaFuncSetAttribute(sparse_conv_tf32,
                             cudaFuncAttributeMaxDynamicSharedMemorySize, SM_TOTAL);
        attr_set = true;
    }

    cudaMemsetAsync(d_out, 0, (size_t)out_size * sizeof(float), 0);

    dim3 grid(CTAS_X, K);
    sparse_conv_tf32<<<grid, THREADS, SM_TOTAL>>>(x, W, in_map, out_map, out, M);
}

// round 15
// speedup vs baseline: 1.1733x; 1.0800x over previous
#include <cuda_runtime.h>
#include <cstddef>
#include <cstdint>

// SparseConv: out[out_map[k,m]] += x[in_map[k,m]] @ W[k]   (K=27, M=65536, Cin=Cout=64)
//
// Round 15 (= R14 resubmit; previous round was an infra failure, kernel never ran):
// TF32 m16n8k8 with ldmatrix-loaded A fragments.
//   - A = raw fp32 x rows in smem (cp.async gather, stride 272B -> conflict-free LDSM)
//   - A fragment = 1x ldmatrix.x4 (b16 ldmatrix on fp32 data; regs permute {r0,r2,r1,r3})
//     + 4x cvt.rna.tf32 (same arithmetic as R13 -> same rel_err ~2.9e-4)
//   - B = W[k]^T tf32, k-interleaved, stride 72 words (conflict-free LDS.64 frags)
//   - no prep kernel, occ 3 (53.2KB smem, launch_bounds(256,3)), grid (16,27)

#define CIN     64
#define COUT    64
#define THREADS 256
#define CTAS_X  16

#define STRA_B   272                 // A row stride bytes (68 words, == 4 banks mod 32)
#define STRB_W   72                  // B row stride words (288B, == 8 banks mod 32)
#define SM_A     0                   // 128 * 272 = 34816 B
#define SM_B     34816               // 64 * 288  = 18432 B
#define SM_TOTAL (34816 + 18432)     // 53248 B -> 3 CTAs/SM

__device__ __forceinline__ uint32_t smem_u32(const void* p) {
    uint32_t a;
    asm("{ .reg .u64 t; cvta.to.shared.u64 t, %1; cvt.u32.u64 %0, t; }" : "=r"(a) : "l"(p));
    return a;
}
__device__ __forceinline__ uint32_t f2tf32(float f) {
    uint32_t u;
    asm("cvt.rna.tf32.f32 %0, %1;" : "=r"(u) : "f"(f));
    return u;
}

#define CP_ASYNC16(dst, src) \
    asm volatile("cp.async.cg.shared.global [%0], [%1], 16;" :: "r"(dst), "l"(src) : "memory")
#define CP_COMMIT()  asm volatile("cp.async.commit_group;" ::: "memory")
#define CP_WAIT0()   asm volatile("cp.async.wait_group 0;" ::: "memory")

#define LDSM_X4(r, addr) \
    asm volatile("ldmatrix.sync.aligned.m8n8.x4.shared.b16 {%0,%1,%2,%3}, [%4];" \
        : "=r"((r)[0]), "=r"((r)[1]), "=r"((r)[2]), "=r"((r)[3]) : "r"(addr))

#define MMA_TF32(c, a0, a1, a2, a3, b0, b1) \
    asm volatile("mma.sync.aligned.m16n8k8.row.col.f32.tf32.tf32.f32 " \
        "{%0,%1,%2,%3}, {%4,%5,%6,%7}, {%8,%9}, {%0,%1,%2,%3};" \
        : "+f"((c)[0]), "+f"((c)[1]), "+f"((c)[2]), "+f"((c)[3]) \
        : "r"(a0), "r"(a1), "r"(a2), "r"(a3), "r"(b0), "r"(b1))

__device__ __forceinline__ void red_add_v4(float* dst, float a, float b, float c, float d) {
    asm volatile("red.global.add.v4.f32 [%0], {%1, %2, %3, %4};"
                 :: "l"(dst), "f"(a), "f"(b), "f"(c), "f"(d) : "memory");
}

__global__ void __launch_bounds__(THREADS, 3) sparse_conv_tf32b(
    const float* __restrict__ x,
    const float* __restrict__ W,
    const int*   __restrict__ in_map,
    const int*   __restrict__ out_map,
    float*       __restrict__ out,
    int M)
{
    extern __shared__ char smem[];
    const uint32_t sb = smem_u32(smem);
    uint32_t* smB = (uint32_t*)(smem + SM_B);
    const int tid  = threadIdx.x;
    const int w    = tid >> 5;
    const int lane = tid & 31;
    const int mg   = w >> 1;        // rows 32*mg .. 32*mg+31
    const int nh   = w & 1;         // cols 32*nh .. 32*nh+31
    const int k    = blockIdx.y;
    const int kM   = k * M;
    const int ntiles = M >> 7;

    // --- stage W[k]^T as tf32, k-interleaved: word[n*72 + s*8 + c],
    //     kg = s*8+kk, c = ((kk&3)<<1)|(kk>>2)  -> B frag = 1 LDS.64 ---
    {
        const float* Wk = W + (size_t)k * (CIN * COUT);
        #pragma unroll
        for (int i = 0; i < (CIN * COUT) / THREADS; i++) {
            const int lin = tid + i * THREADS;
            const int kg = lin >> 6, n = lin & 63;
            const int s = kg >> 3, kk = kg & 7;
            const int c = ((kk & 3) << 1) | (kk >> 2);
            smB[n * STRB_W + s * 8 + c] = f2tf32(Wk[(size_t)kg * COUT + n]);
        }
    }

    // A ldmatrix base (byte address), x4 matrices:
    //   m0: rows 0-7 cols 0-3 | m1: rows 0-7 cols 4-7 | m2: rows 8-15 c0-3 | m3: rows 8-15 c4-7
    //   lanes 0-7 -> m0 row addrs, 8-15 -> m1, 16-23 -> m2, 24-31 -> m3
    const int arow_l = 32 * mg + (lane & 7) + ((lane & 16) >> 1);
    const uint32_t aBase = sb + SM_A + (uint32_t)(arow_l * STRA_B + ((lane & 8) << 1));
    // B fragment word base: lane -> row (nh*32 + (L>>2)), word pair 2*(L&3)
    const int bwrd = (nh * 32 + (lane >> 2)) * STRB_W + (lane & 3) * 2;

    // epilogue lane mapping
    const bool odd = (lane & 1);
    const int  er0 = 32 * mg + (lane >> 2) + (odd ? 8 : 0);
    const int  q0  = (lane & 2) * 2;

    for (int mt = blockIdx.x; mt < ntiles; mt += CTAS_X) {
        const int m0 = mt << 7;

        // epilogue rows: issue LDG early (in flight through gather + MMA)
        const int orow0 = out_map[kM + m0 + er0];
        const int orow1 = out_map[kM + m0 + er0 + 16];

        __syncthreads();   // previous tile's readers done before overwrite

        // --- gather: cp.async 128 fp32 x-rows (16B chunks, 8/thread) ---
        #pragma unroll
        for (int j = 0; j < 8; j++) {
            const int f = tid + j * THREADS;
            const int e = f >> 4, q = f & 15;
            const int row = in_map[kM + m0 + e];
            CP_ASYNC16(sb + SM_A + (uint32_t)(e * STRA_B + q * 16),
                       x + (size_t)row * CIN + q * 4);
        }
        CP_COMMIT();
        CP_WAIT0();
        __syncthreads();

        // --- MMA: 8 k-steps x 2 m-tiles x 4 n8-tiles = 64 mma/warp ---
        float acc[2][4][4];
        #pragma unroll
        for (int t = 0; t < 2; t++)
            #pragma unroll
            for (int j = 0; j < 4; j++)
                #pragma unroll
                for (int i = 0; i < 4; i++) acc[t][j][i] = 0.0f;

        #pragma unroll
        for (int ks = 0; ks < 8; ks++) {
            // B fragments: 4 n8 tiles, one LDS.64 each (conflict-free)
            uint32_t bf[4][2];
            #pragma unroll
            for (int p = 0; p < 4; p++) {
                const uint2 bv = *(const uint2*)(smB + bwrd + p * 8 * STRB_W + ks * 8);
                bf[p][0] = bv.x; bf[p][1] = bv.y;
            }
            #pragma unroll
            for (int t = 0; t < 2; t++) {
                uint32_t r[4];
                LDSM_X4(r, aBase + (uint32_t)(t * 16 * STRA_B + ks * 32));
                // tf32 frag = {r0, r2, r1, r3}, rounded
                const uint32_t a0 = f2tf32(__uint_as_float(r[0]));
                const uint32_t a1 = f2tf32(__uint_as_float(r[2]));
                const uint32_t a2 = f2tf32(__uint_as_float(r[1]));
                const uint32_t a3 = f2tf32(__uint_as_float(r[3]));
                #pragma unroll
                for (int p = 0; p < 4; p++)
                    MMA_TF32(acc[t][p], a0, a1, a2, a3, bf[p][0], bf[p][1]);
            }
        }

        // --- epilogue: shfl pair-swap -> red.global.add.v4 ---
        #pragma unroll
        for (int t = 0; t < 2; t++) {
            const int orow = t ? orow1 : orow0;
            float* obase = out + (size_t)orow * COUT + nh * 32 + q0;
            #pragma unroll
            for (int j = 0; j < 4; j++) {
                float* c = acc[t][j];
                const float s0 = __shfl_xor_sync(0xFFFFFFFFu, c[0], 1);
                const float s1 = __shfl_xor_sync(0xFFFFFFFFu, c[1], 1);
                const float s2 = __shfl_xor_sync(0xFFFFFFFFu, c[2], 1);
                const float s3 = __shfl_xor_sync(0xFFFFFFFFu, c[3], 1);
                const float v0 = odd ? s2 : c[0];
                const float v1 = odd ? s3 : c[1];
                const float v2 = odd ? c[2] : s0;
                const float v3 = odd ? c[3] : s1;
                red_add_v4(obase + 8 * j, v0, v1, v2, v3);
            }
        }
    }
}

extern "C" void kernel_launch(void* const* d_in, const int* in_sizes, int n_in,
                              void* d_out, int out_size)
{
    const float* x       = (const float*)d_in[0];
    const float* W       = (const float*)d_in[1];
    const int*   in_map  = (const int*)d_in[2];
    const int*   out_map = (const int*)d_in[3];
    float*       out     = (float*)d_out;

    const int K = in_sizes[1] / (CIN * COUT);   // 27
    const int M = in_sizes[2] / K;              // 65536

    static bool attr_set = false;
    if (!attr_set) {
        cudaFuncSetAttribute(sparse_conv_tf32b,
                             cudaFuncAttributeMaxDynamicSharedMemorySize, SM_TOTAL);
        attr_set = true;
    }

    cudaMemsetAsync(d_out, 0, (size_t)out_size * sizeof(float), 0);

    dim3 grid(CTAS_X, K);
    sparse_conv_tf32b<<<grid, THREADS, SM_TOTAL>>>(x, W, in_map, out_map, out, M);
}

// round 16
// speedup vs baseline: 1.3427x; 1.1444x over previous
#include <cuda_runtime.h>
#include <cuda_fp16.h>
#include <cstddef>
#include <cstdint>

// SparseConv: out[out_map[k,m]] += x[in_map[k,m]] @ W[k]   (K=27, M=65536, Cin=Cout=64)
//
// Round 16: single-pass FP16 m16n8k16 (fp32 accumulate).
//   fp16 mantissa (10b) == tf32 mantissa -> expected rel_err ~3e-4 (gate 1e-3).
//   - prep kernel: x fp32 -> fp16 global copy (33MB) + zero out, one launch
//   - A = fp16 x rows, cp.async gather 1024x16B/tile (half of tf32's traffic)
//   - A/B fragments via ldmatrix (R8's proven conflict-free 144B-stride geometry)
//   - 32 mma/warp/tile (vs 64 tf32 / 96 bf16-3term), zero in-loop cvt
//   - occ 3 (27.6KB smem, launch_bounds(256,3)), grid (16,27)

#define CIN     64
#define COUT    64
#define THREADS 256
#define CTAS_X  16

#define STRIDE_A 144                 // bytes per A row (64 halves = 128B + 16B pad)
#define STRIDE_B 144

#define SM_A     0                   // 128 * 144 = 18432 B
#define SM_B     18432               // 64 * 144  =  9216 B
#define SM_TOTAL (18432 + 9216)      // 27648 B -> 3 CTAs/SM (regs-bound)

// global scratch: fp16 copy of x (128 B per row)
#define NMAX_HALF (262144 * 64)
__device__ __align__(16) __half g_xh[NMAX_HALF];

__device__ __forceinline__ uint32_t smem_u32(const void* p) {
    uint32_t a;
    asm("{ .reg .u64 t; cvta.to.shared.u64 t, %1; cvt.u32.u64 %0, t; }" : "=r"(a) : "l"(p));
    return a;
}

#define CP_ASYNC16(dst, src) \
    asm volatile("cp.async.cg.shared.global [%0], [%1], 16;" :: "r"(dst), "l"(src) : "memory")
#define CP_COMMIT()  asm volatile("cp.async.commit_group;" ::: "memory")
#define CP_WAIT0()   asm volatile("cp.async.wait_group 0;" ::: "memory")

#define LDSM_X4(r, addr) \
    asm volatile("ldmatrix.sync.aligned.m8n8.x4.shared.b16 {%0,%1,%2,%3}, [%4];" \
        : "=r"((r)[0]), "=r"((r)[1]), "=r"((r)[2]), "=r"((r)[3]) : "r"(addr))

#define LDSM_X4_T(r, addr) \
    asm volatile("ldmatrix.sync.aligned.m8n8.x4.trans.shared.b16 {%0,%1,%2,%3}, [%4];" \
        : "=r"((r)[0]), "=r"((r)[1]), "=r"((r)[2]), "=r"((r)[3]) : "r"(addr))

#define MMA_F16(c, a, b0, b1) \
    asm volatile("mma.sync.aligned.m16n8k16.row.col.f32.f16.f16.f32 " \
        "{%0,%1,%2,%3}, {%4,%5,%6,%7}, {%8,%9}, {%0,%1,%2,%3};" \
        : "+f"((c)[0]), "+f"((c)[1]), "+f"((c)[2]), "+f"((c)[3]) \
        : "r"((a)[0]), "r"((a)[1]), "r"((a)[2]), "r"((a)[3]), "r"(b0), "r"(b1))

__device__ __forceinline__ void red_add_v4(float* dst, float a, float b, float c, float d) {
    asm volatile("red.global.add.v4.f32 [%0], {%1, %2, %3, %4};"
                 :: "l"(dst), "f"(a), "f"(b), "f"(c), "f"(d) : "memory");
}

// ---------- prep: zero out + convert x fp32 -> fp16 (one launch) ----------
__global__ void __launch_bounds__(256) prep_kernel(
    const float* __restrict__ x, float* __restrict__ out, int total8, int out4)
{
    const int i = blockIdx.x * 256 + threadIdx.x;
    if (i < out4) ((float4*)out)[i] = make_float4(0.f, 0.f, 0.f, 0.f);
    if (i < total8) {
        const float4 v0 = ((const float4*)x)[2 * i];
        const float4 v1 = ((const float4*)x)[2 * i + 1];
        const __half2 h0 = __floats2half2_rn(v0.x, v0.y);
        const __half2 h1 = __floats2half2_rn(v0.z, v0.w);
        const __half2 h2 = __floats2half2_rn(v1.x, v1.y);
        const __half2 h3 = __floats2half2_rn(v1.z, v1.w);
        uint4 o;
        o.x = *(const uint32_t*)&h0;
        o.y = *(const uint32_t*)&h1;
        o.z = *(const uint32_t*)&h2;
        o.w = *(const uint32_t*)&h3;
        ((uint4*)g_xh)[i] = o;
    }
}

// ---------- main kernel ----------
__global__ void __launch_bounds__(THREADS, 3) sparse_conv_f16(
    const float* __restrict__ W,
    const int*   __restrict__ in_map,
    const int*   __restrict__ out_map,
    float*       __restrict__ out,
    int M)
{
    extern __shared__ char smem[];
    const uint32_t sb = smem_u32(smem);
    const int tid  = threadIdx.x;
    const int w    = tid >> 5;
    const int lane = tid & 31;
    const int mg   = w >> 1;        // rows 32*mg .. 32*mg+31
    const int nh   = w & 1;         // cols 32*nh .. 32*nh+31
    const int k    = blockIdx.y;
    const int kM   = k * M;
    const int ntiles = M >> 7;

    // --- stage W[k] -> fp16 in smem, [cin][cout] rows, 144B stride ---
    {
        const float* Wk = W + (size_t)k * (CIN * COUT);
        #pragma unroll
        for (int i = 0; i < (CIN * COUT) / THREADS; i++) {
            const int lin = tid + i * THREADS;
            const int c = lin >> 6, n = lin & 63;
            *(__half*)(smem + SM_B + (uint32_t)(c * STRIDE_B + n * 2)) =
                __float2half_rn(Wk[lin]);
        }
    }

    // fragment addressing (R8 geometry)
    const uint32_t b_off = (uint32_t)((lane & 15) * STRIDE_B + (lane >> 4) * 16 + nh * 64);
    const uint32_t bB = sb + SM_B + b_off;
    const uint32_t a_off = (uint32_t)((32 * mg + (lane & 15)) * STRIDE_A + (lane >> 4) * 16);
    const uint32_t aB = sb + SM_A + a_off;

    // epilogue lane mapping
    const bool odd = (lane & 1);
    const int  er0 = 32 * mg + (lane >> 2) + (odd ? 8 : 0);
    const int  q0  = (lane & 2) * 2;

    const char* xhB = (const char*)g_xh;

    for (int mt = blockIdx.x; mt < ntiles; mt += CTAS_X) {
        const int m0 = mt << 7;

        // epilogue rows (LDG in flight through gather + MMA)
        const int orow0 = out_map[kM + m0 + er0];
        const int orow1 = out_map[kM + m0 + er0 + 16];

        __syncthreads();   // previous tile's LDSM readers done before overwrite

        // --- gather: cp.async 128 fp16 rows (8 x 16B chunks each, 4/thread) ---
        #pragma unroll
        for (int j = 0; j < 4; j++) {
            const int f = tid + j * THREADS;
            const int e = f >> 3, c = f & 7;
            const int row = in_map[kM + m0 + e];
            CP_ASYNC16(sb + SM_A + (uint32_t)(e * STRIDE_A + c * 16),
                       xhB + (size_t)row * 128 + c * 16);
        }
        CP_COMMIT();
        CP_WAIT0();
        __syncthreads();

        // --- MMA: 4 k-steps x 2 m-tiles x 4 n8-tiles = 32 mma/warp ---
        float acc[2][4][4];
        #pragma unroll
        for (int t = 0; t < 2; t++)
            #pragma unroll
            for (int j = 0; j < 4; j++)
                #pragma unroll
                for (int i = 0; i < 4; i++) acc[t][j][i] = 0.0f;

        #pragma unroll
        for (int s = 0; s < 4; s++) {
            uint32_t bh[2][4];
            const uint32_t so = (uint32_t)(s * 16 * STRIDE_B);
            LDSM_X4_T(bh[0], bB + so);
            LDSM_X4_T(bh[1], bB + so + 32);
            #pragma unroll
            for (int t = 0; t < 2; t++) {
                uint32_t ah[4];
                LDSM_X4(ah, aB + (uint32_t)(t * 16 * STRIDE_A + s * 32));
                #pragma unroll
                for (int p = 0; p < 2; p++) {
                    MMA_F16(acc[t][2 * p],     ah, bh[p][0], bh[p][1]);
                    MMA_F16(acc[t][2 * p + 1], ah, bh[p][2], bh[p][3]);
                }
            }
        }

        // --- epilogue: shfl pair-swap -> red.global.add.v4 ---
        #pragma unroll
        for (int t = 0; t < 2; t++) {
            const int orow = t ? orow1 : orow0;
            float* obase = out + (size_t)orow * COUT + nh * 32 + q0;
            #pragma unroll
            for (int j = 0; j < 4; j++) {
                float* c = acc[t][j];
                const float s0 = __shfl_xor_sync(0xFFFFFFFFu, c[0], 1);
                const float s1 = __shfl_xor_sync(0xFFFFFFFFu, c[1], 1);
                const float s2 = __shfl_xor_sync(0xFFFFFFFFu, c[2], 1);
                const float s3 = __shfl_xor_sync(0xFFFFFFFFu, c[3], 1);
                const float v0 = odd ? s2 : c[0];
                const float v1 = odd ? s3 : c[1];
                const float v2 = odd ? c[2] : s0;
                const float v3 = odd ? c[3] : s1;
                red_add_v4(obase + 8 * j, v0, v1, v2, v3);
            }
        }
    }
}

extern "C" void kernel_launch(void* const* d_in, const int* in_sizes, int n_in,
                              void* d_out, int out_size)
{
    const float* x       = (const float*)d_in[0];
    const float* W       = (const float*)d_in[1];
    const int*   in_map  = (const int*)d_in[2];
    const int*   out_map = (const int*)d_in[3];
    float*       out     = (float*)d_out;

    const int K = in_sizes[1] / (CIN * COUT);   // 27
    const int M = in_sizes[2] / K;              // 65536
    const int total8 = in_sizes[0] / 8;
    const int out4   = out_size / 4;
    const int pmax   = total8 > out4 ? total8 : out4;

    static bool attr_set = false;
    if (!attr_set) {
        cudaFuncSetAttribute(sparse_conv_f16,
                             cudaFuncAttributeMaxDynamicSharedMemorySize, SM_TOTAL);
        attr_set = true;
    }

    prep_kernel<<<(pmax + 255) / 256, 256>>>(x, out, total8, out4);

    dim3 grid(CTAS_X, K);
    sparse_conv_f16<<<grid, THREADS, SM_TOTAL>>>(W, in_map, out_map, out, M);
}